// round 15
// baseline (speedup 1.0000x reference)
#include <cuda_runtime.h>
#include <math.h>

#define BB 4
#define VV 8192
#define FF 16384
#define NN 8192
#define SS 32                      // F-chunks per batch
#define CHUNK (FF / SS)            // 512 faces per block
#define NPAIR (CHUNK / 2)          // 256 face-pairs per tile
#define NG16 (CHUNK / 16)          // 32 groups of 16 faces
#define SCAN_THREADS 128
#define PT 8                       // points per thread
#define PTS_PER_BLOCK (SCAN_THREADS * PT)   // 1024
#define EPS_C 1e-3f
#define WEIGHT_C 1000.0

// ---- scratch (no allocations allowed) ----
__device__ float4 g_c4[BB * FF];        // (cx, cy, cz, |c|^2)
__device__ float4 g_nrm[BB * FF];       // unit normal
__device__ unsigned long long g_minkey[BB * NN];  // (sortable score | group base)
__device__ double g_acc[2];             // [0]=sum interp^3, [1]=count(interp>0)
__device__ int    g_done;

// ---- packed f32x2 helpers (sm_103a) ----
__device__ __forceinline__ unsigned long long pack2(float lo, float hi) {
    unsigned long long r;
    asm("mov.b64 %0, {%1, %2};" : "=l"(r) : "f"(lo), "f"(hi));
    return r;
}
__device__ __forceinline__ unsigned long long fma2(unsigned long long a,
                                                   unsigned long long b,
                                                   unsigned long long c) {
    unsigned long long d;
    asm("fma.rn.f32x2 %0, %1, %2, %3;" : "=l"(d) : "l"(a), "l"(b), "l"(c));
    return d;
}
__device__ __forceinline__ void unpack2(unsigned long long v, float& lo, float& hi) {
    asm("mov.b64 {%0, %1}, %2;" : "=f"(lo), "=f"(hi) : "l"(v));
}

// One thread per face: center, |center|^2, unit normal. Also inits g_minkey
// (BB*NN entries <= BB*FF threads) and accumulators.
__global__ void faces_kernel(const float* __restrict__ opos,
                             const int* __restrict__ faces) {
    int t = blockIdx.x * blockDim.x + threadIdx.x;
    if (t == 0) { g_acc[0] = 0.0; g_acc[1] = 0.0; g_done = 0; }
    if (t < BB * NN) g_minkey[t] = ~0ull;
    if (t >= BB * FF) return;
    int b = t / FF;
    const int* fp = faces + (size_t)t * 3;
    int i0 = fp[0], i1 = fp[1], i2 = fp[2];
    const float* pb = opos + (size_t)b * VV * 3;

    float x0 = __ldg(pb + i0 * 3 + 0), y0 = __ldg(pb + i0 * 3 + 1), z0 = __ldg(pb + i0 * 3 + 2);
    float x1 = __ldg(pb + i1 * 3 + 0), y1 = __ldg(pb + i1 * 3 + 1), z1 = __ldg(pb + i1 * 3 + 2);
    float x2 = __ldg(pb + i2 * 3 + 0), y2 = __ldg(pb + i2 * 3 + 1), z2 = __ldg(pb + i2 * 3 + 2);

    const float third = 1.0f / 3.0f;
    float cx = (x0 + x1 + x2) * third;
    float cy = (y0 + y1 + y2) * third;
    float cz = (z0 + z1 + z2) * third;

    float e1x = x1 - x0, e1y = y1 - y0, e1z = z1 - z0;
    float e2x = x2 - x0, e2y = y2 - y0, e2z = z2 - z0;
    float nx = e1y * e2z - e1z * e2y;
    float ny = e1z * e2x - e1x * e2z;
    float nz = e1x * e2y - e1y * e2x;
    float len = sqrtf(nx * nx + ny * ny + nz * nz);
    float inv = 1.0f / fmaxf(len, 1e-12f);

    g_c4[t]  = make_float4(cx, cy, cz, cx * cx + cy * cy + cz * cz);
    g_nrm[t] = make_float4(nx * inv, ny * inv, nz * inv, 0.0f);
}

// Score 8 faces (4 smem pairs at tbase+m0) for point k, return their min.
// Exact per-lane fma.rn chain: ((qz*z + w) + qy*y) + qx*x.
__device__ __forceinline__ float score8(const ulonglong2* tA, const ulonglong2* tB,
                                        int m0, unsigned long long qx,
                                        unsigned long long qy, unsigned long long qz) {
    ulonglong2 a0 = tA[m0 + 0], v0 = tB[m0 + 0];
    ulonglong2 a1 = tA[m0 + 1], v1 = tB[m0 + 1];
    ulonglong2 a2 = tA[m0 + 2], v2 = tB[m0 + 2];
    ulonglong2 a3 = tA[m0 + 3], v3 = tB[m0 + 3];
    unsigned long long s0 = fma2(qz, v0.x, v0.y);
    unsigned long long s1 = fma2(qz, v1.x, v1.y);
    unsigned long long s2 = fma2(qz, v2.x, v2.y);
    unsigned long long s3 = fma2(qz, v3.x, v3.y);
    s0 = fma2(qy, a0.y, s0);
    s1 = fma2(qy, a1.y, s1);
    s2 = fma2(qy, a2.y, s2);
    s3 = fma2(qy, a3.y, s3);
    s0 = fma2(qx, a0.x, s0);
    s1 = fma2(qx, a1.x, s1);
    s2 = fma2(qx, a2.x, s2);
    s3 = fma2(qx, a3.x, s3);
    float l0, h0, l1, h1, l2, h2, l3, h3;
    unpack2(s0, l0, h0);
    unpack2(s1, l1, h1);
    unpack2(s2, l2, h2);
    unpack2(s3, l3, h3);
    float p0 = fminf(l0, h0);
    float p1 = fminf(l1, h1);
    float p2 = fminf(l2, h2);
    float p3 = fminf(l3, h3);
    return fminf(fminf(p0, p1), fminf(p2, p3));
}

// Each block: 1024 points x 512-face chunk (grid 8x32x4 = 1024 blocks).
// Inner loop scores a GROUP of 16 faces (two 8-face sub-trees sharing operand
// registers) with ONE compare-select per group tracking (group_min, base).
// Chunk results are merged GLOBALLY via atomicMin on a packed 64-bit key
// (monotone score bits << 32 | group base): min over keys == min score with
// lowest group base on ties == JAX first-index argmin at group granularity.
// First-index recovery within the winning 16-face group happens in
// reduce_kernel via exact bit-equality rescan.
__global__ __launch_bounds__(SCAN_THREADS)
void scan_kernel(const float* __restrict__ pred) {
    __shared__ ulonglong2 tA[NPAIR];   // ((x,x'),(y,y'))
    __shared__ ulonglong2 tB[NPAIR];   // ((z,z'),(w,w'))

    int b = blockIdx.z;
    int s = blockIdx.y;
    int pbase = blockIdx.x * PTS_PER_BLOCK;
    int tid = threadIdx.x;
    int fbase = s * CHUNK;

    const float4* cbase = g_c4 + (size_t)b * FF + fbase;
    for (int m = tid; m < NPAIR; m += SCAN_THREADS) {
        float4 c0 = cbase[2 * m];
        float4 c1 = cbase[2 * m + 1];
        tA[m].x = pack2(c0.x, c1.x);
        tA[m].y = pack2(c0.y, c1.y);
        tB[m].x = pack2(c0.z, c1.z);
        tB[m].y = pack2(c0.w, c1.w);
    }

    // q = -2p broadcast-packed per point.
    unsigned long long qx2[PT], qy2[PT], qz2[PT];
    float best[PT];
    int bidx[PT];
#pragma unroll
    for (int k = 0; k < PT; k++) {
        int n = pbase + k * SCAN_THREADS + tid;
        const float* pp = pred + ((size_t)b * NN + n) * 3;
        float qx = -2.0f * __ldg(pp + 0);
        float qy = -2.0f * __ldg(pp + 1);
        float qz = -2.0f * __ldg(pp + 2);
        qx2[k] = pack2(qx, qx);
        qy2[k] = pack2(qy, qy);
        qz2[k] = pack2(qz, qz);
        best[k] = 3.4e38f;
        bidx[k] = 0;
    }
    __syncthreads();

    float mgA[PT];
    for (int g = 0; g < NG16; g++) {
        int m0 = g * 8;
        int jv = fbase + 16 * g;
        // first 8 faces
#pragma unroll
        for (int k = 0; k < PT; k++)
            mgA[k] = score8(tA, tB, m0, qx2[k], qy2[k], qz2[k]);
        // second 8 faces + combine + single select per 16 faces
#pragma unroll
        for (int k = 0; k < PT; k++) {
            float mgB = score8(tA, tB, m0 + 4, qx2[k], qy2[k], qz2[k]);
            float mg = fminf(mgA[k], mgB);
            if (mg < best[k]) { best[k] = mg; bidx[k] = jv; }
        }
    }

    // Global merge: packed sortable key, REDG.MIN.U64 (no return).
#pragma unroll
    for (int k = 0; k < PT; k++) {
        int n = pbase + k * SCAN_THREADS + tid;
        unsigned int sb = __float_as_uint(best[k]);
        unsigned int kb = (sb & 0x80000000u) ? ~sb : (sb | 0x80000000u);
        unsigned long long key = ((unsigned long long)kb << 32)
                               | (unsigned int)bidx[k];
        atomicMin(&g_minkey[(size_t)b * NN + n], key);
    }
}

// Decode winning (score, group) per point, recover first-index within the
// 16-face group by exact bit-equality rescan, hinge loss, reduce.
// Last block finalizes d_out.
__global__ __launch_bounds__(128)
void reduce_kernel(const float* __restrict__ pred, float* __restrict__ out,
                   int nblocks) {
    __shared__ double s_loss[4];
    __shared__ double s_cnt[4];

    int t = blockIdx.x * blockDim.x + threadIdx.x;   // [0, BB*NN)
    int b = t / NN;

    unsigned long long key = g_minkey[t];
    unsigned int kb = (unsigned int)(key >> 32);
    unsigned int sb = (kb & 0x80000000u) ? (kb & 0x7FFFFFFFu) : ~kb;
    int gbase = (int)(unsigned int)(key & 0xFFFFFFFFu);

    const float* pp = pred + (size_t)t * 3;
    float px = __ldg(pp + 0), py = __ldg(pp + 1), pz = __ldg(pp + 2);
    float qx = -2.0f * px, qy = -2.0f * py, qz = -2.0f * pz;

    // Recover first matching index within the winning group of 16. FMNMX
    // propagates exact lane bits and scalar fma.rn == per-lane fma.rn.f32x2,
    // so bit-equality finds the true winner; min over ascending candidate
    // indices == first index (JAX tie-break).
    int widx = 0x7fffffff;
    const float4* cb = g_c4 + (size_t)b * FF;
#pragma unroll
    for (int jj = 0; jj < 16; jj++) {
        float4 cj = cb[gbase + jj];
        float sj = fmaf(qx, cj.x, fmaf(qy, cj.y, fmaf(qz, cj.z, cj.w)));
        int cand = (__float_as_uint(sj) == sb) ? (gbase + jj) : 0x7fffffff;
        widx = min(widx, cand);
    }
    if (widx == 0x7fffffff) widx = gbase;   // unreachable safety guard

    float4 c  = g_c4[(size_t)b * FF + widx];
    float4 nr = g_nrm[(size_t)b * FF + widx];
    float d = (px - c.x) * nr.x + (py - c.y) * nr.y + (pz - c.z) * nr.z;
    float interp = fmaxf(EPS_C - d, 0.0f);

    double l  = (double)(interp * interp * interp);
    double cc = (interp > 0.0f) ? 1.0 : 0.0;

    int lane = threadIdx.x & 31;
    int warp = threadIdx.x >> 5;
#pragma unroll
    for (int off = 16; off > 0; off >>= 1) {
        l  += __shfl_down_sync(0xffffffffu, l, off);
        cc += __shfl_down_sync(0xffffffffu, cc, off);
    }
    if (lane == 0) { s_loss[warp] = l; s_cnt[warp] = cc; }
    __syncthreads();
    if (warp == 0 && lane == 0) {
        double L = s_loss[0] + s_loss[1] + s_loss[2] + s_loss[3];
        double C = s_cnt[0] + s_cnt[1] + s_cnt[2] + s_cnt[3];
        atomicAdd(&g_acc[0], L);
        atomicAdd(&g_acc[1], C);
        __threadfence();
        int done = atomicAdd(&g_done, 1);
        if (done == nblocks - 1) {
            double totL = atomicAdd(&g_acc[0], 0.0);
            double totC = atomicAdd(&g_acc[1], 0.0);
            out[0] = (float)(totL / (double)BB * WEIGHT_C);
            out[1] = (float)(totC / (double)(BB * NN));
        }
    }
}

extern "C" void kernel_launch(void* const* d_in, const int* in_sizes, int n_in,
                              void* d_out, int out_size) {
    const float* pred  = (const float*)d_in[0];   // [B,N,3] f32
    const float* opos  = (const float*)d_in[1];   // [B,V,3] f32
    const int*   faces = (const int*)d_in[2];     // [B,F,3] i32
    float* out = (float*)d_out;

    faces_kernel<<<(BB * FF + 255) / 256, 256>>>(opos, faces);
    scan_kernel<<<dim3(NN / PTS_PER_BLOCK, SS, BB), SCAN_THREADS>>>(pred);
    int rblocks = (BB * NN) / 128;
    reduce_kernel<<<rblocks, 128>>>(pred, out, rblocks);
}

// round 16
// speedup vs baseline: 1.0240x; 1.0240x over previous
#include <cuda_runtime.h>
#include <math.h>

#define BB 4
#define VV 8192
#define FF 16384
#define NN 8192
#define SS 32                      // F-chunks per batch
#define CHUNK (FF / SS)            // 512 faces per block
#define NPAIR (CHUNK / 2)          // 256 face-pairs per tile
#define NGROUP (NPAIR / 4)         // 64 groups of 8 faces
#define SCAN_THREADS 128
#define PT 8                       // points per thread
#define PTS_PER_BLOCK (SCAN_THREADS * PT)   // 1024
#define EPS_C 1e-3f
#define WEIGHT_C 1000.0

// ---- scratch (no allocations allowed) ----
__device__ float4 g_c4[BB * FF];        // (cx, cy, cz, |c|^2)
__device__ float4 g_nrm[BB * FF];       // unit normal
__device__ unsigned long long g_minkey[BB * NN];  // (sortable score | group base)
__device__ double g_acc[2];             // [0]=sum interp^3, [1]=count(interp>0)
__device__ int    g_done;

// ---- packed f32x2 helpers (sm_103a) ----
__device__ __forceinline__ unsigned long long pack2(float lo, float hi) {
    unsigned long long r;
    asm("mov.b64 %0, {%1, %2};" : "=l"(r) : "f"(lo), "f"(hi));
    return r;
}
__device__ __forceinline__ unsigned long long fma2(unsigned long long a,
                                                   unsigned long long b,
                                                   unsigned long long c) {
    unsigned long long d;
    asm("fma.rn.f32x2 %0, %1, %2, %3;" : "=l"(d) : "l"(a), "l"(b), "l"(c));
    return d;
}
__device__ __forceinline__ void unpack2(unsigned long long v, float& lo, float& hi) {
    asm("mov.b64 {%0, %1}, %2;" : "=f"(lo), "=f"(hi) : "l"(v));
}

// One thread per face: center, |center|^2, unit normal. Also inits g_minkey
// (BB*NN entries <= BB*FF threads) and accumulators.
__global__ void faces_kernel(const float* __restrict__ opos,
                             const int* __restrict__ faces) {
    int t = blockIdx.x * blockDim.x + threadIdx.x;
    if (t == 0) { g_acc[0] = 0.0; g_acc[1] = 0.0; g_done = 0; }
    if (t < BB * NN) g_minkey[t] = ~0ull;
    if (t >= BB * FF) return;
    int b = t / FF;
    const int* fp = faces + (size_t)t * 3;
    int i0 = fp[0], i1 = fp[1], i2 = fp[2];
    const float* pb = opos + (size_t)b * VV * 3;

    float x0 = __ldg(pb + i0 * 3 + 0), y0 = __ldg(pb + i0 * 3 + 1), z0 = __ldg(pb + i0 * 3 + 2);
    float x1 = __ldg(pb + i1 * 3 + 0), y1 = __ldg(pb + i1 * 3 + 1), z1 = __ldg(pb + i1 * 3 + 2);
    float x2 = __ldg(pb + i2 * 3 + 0), y2 = __ldg(pb + i2 * 3 + 1), z2 = __ldg(pb + i2 * 3 + 2);

    const float third = 1.0f / 3.0f;
    float cx = (x0 + x1 + x2) * third;
    float cy = (y0 + y1 + y2) * third;
    float cz = (z0 + z1 + z2) * third;

    float e1x = x1 - x0, e1y = y1 - y0, e1z = z1 - z0;
    float e2x = x2 - x0, e2y = y2 - y0, e2z = z2 - z0;
    float nx = e1y * e2z - e1z * e2y;
    float ny = e1z * e2x - e1x * e2z;
    float nz = e1x * e2y - e1y * e2x;
    float len = sqrtf(nx * nx + ny * ny + nz * nz);
    float inv = 1.0f / fmaxf(len, 1e-12f);

    g_c4[t]  = make_float4(cx, cy, cz, cx * cx + cy * cy + cz * cz);
    g_nrm[t] = make_float4(nx * inv, ny * inv, nz * inv, 0.0f);
}

// Each block: 1024 points x 512-face chunk (grid 8x32x4 = 1024 blocks).
// SMEM tile packs FACE PAIRS as f32x2 words. Inner loop: load ONE group of
// 8 faces (4 pairs = 8 LDS.128) into registers ONCE, then score all PT=8
// points against it (12 FFMA2 + 7-FMNMX tree + 1 compare-select per point).
// Chunk results merge GLOBALLY via atomicMin on a packed 64-bit key
// (monotone score bits << 32 | group base): min over keys == min score with
// lowest group base on ties == JAX first-index argmin at group granularity.
// First-index recovery within the winning 8-face group happens in
// reduce_kernel via exact bit-equality rescan.
__global__ __launch_bounds__(SCAN_THREADS)
void scan_kernel(const float* __restrict__ pred) {
    __shared__ ulonglong2 tA[NPAIR];   // ((x,x'),(y,y'))
    __shared__ ulonglong2 tB[NPAIR];   // ((z,z'),(w,w'))

    int b = blockIdx.z;
    int s = blockIdx.y;
    int pbase = blockIdx.x * PTS_PER_BLOCK;
    int tid = threadIdx.x;
    int fbase = s * CHUNK;

    const float4* cbase = g_c4 + (size_t)b * FF + fbase;
    for (int m = tid; m < NPAIR; m += SCAN_THREADS) {
        float4 c0 = cbase[2 * m];
        float4 c1 = cbase[2 * m + 1];
        tA[m].x = pack2(c0.x, c1.x);
        tA[m].y = pack2(c0.y, c1.y);
        tB[m].x = pack2(c0.z, c1.z);
        tB[m].y = pack2(c0.w, c1.w);
    }

    // q = -2p broadcast-packed per point.
    unsigned long long qx2[PT], qy2[PT], qz2[PT];
    float best[PT];
    int bidx[PT];
#pragma unroll
    for (int k = 0; k < PT; k++) {
        int n = pbase + k * SCAN_THREADS + tid;
        const float* pp = pred + ((size_t)b * NN + n) * 3;
        float qx = -2.0f * __ldg(pp + 0);
        float qy = -2.0f * __ldg(pp + 1);
        float qz = -2.0f * __ldg(pp + 2);
        qx2[k] = pack2(qx, qx);
        qy2[k] = pack2(qy, qy);
        qz2[k] = pack2(qz, qz);
        best[k] = 3.4e38f;
        bidx[k] = 0;
    }
    __syncthreads();

#pragma unroll 2
    for (int g = 0; g < NGROUP; g++) {
        int m0 = g * 4;
        // group operands loaded ONCE, reused by all PT points from registers
        ulonglong2 a0 = tA[m0 + 0], v0 = tB[m0 + 0];
        ulonglong2 a1 = tA[m0 + 1], v1 = tB[m0 + 1];
        ulonglong2 a2 = tA[m0 + 2], v2 = tB[m0 + 2];
        ulonglong2 a3 = tA[m0 + 3], v3 = tB[m0 + 3];
        int jv = fbase + 8 * g;
#pragma unroll
        for (int k = 0; k < PT; k++) {
            // per-lane: ((qz*z + w) + qy*y) + qx*x — same fma order as R1
            unsigned long long s0 = fma2(qz2[k], v0.x, v0.y);
            unsigned long long s1 = fma2(qz2[k], v1.x, v1.y);
            unsigned long long s2 = fma2(qz2[k], v2.x, v2.y);
            unsigned long long s3 = fma2(qz2[k], v3.x, v3.y);
            s0 = fma2(qy2[k], a0.y, s0);
            s1 = fma2(qy2[k], a1.y, s1);
            s2 = fma2(qy2[k], a2.y, s2);
            s3 = fma2(qy2[k], a3.y, s3);
            s0 = fma2(qx2[k], a0.x, s0);
            s1 = fma2(qx2[k], a1.x, s1);
            s2 = fma2(qx2[k], a2.x, s2);
            s3 = fma2(qx2[k], a3.x, s3);
            float l0, h0, l1, h1, l2, h2, l3, h3;
            unpack2(s0, l0, h0);
            unpack2(s1, l1, h1);
            unpack2(s2, l2, h2);
            unpack2(s3, l3, h3);
            float p0 = fminf(l0, h0);
            float p1 = fminf(l1, h1);
            float p2 = fminf(l2, h2);
            float p3 = fminf(l3, h3);
            float mg = fminf(fminf(p0, p1), fminf(p2, p3));
            if (mg < best[k]) { best[k] = mg; bidx[k] = jv; }
        }
    }

    // Global merge: packed sortable key, REDG.MIN.U64 (no return).
#pragma unroll
    for (int k = 0; k < PT; k++) {
        int n = pbase + k * SCAN_THREADS + tid;
        unsigned int sb = __float_as_uint(best[k]);
        unsigned int kb = (sb & 0x80000000u) ? ~sb : (sb | 0x80000000u);
        unsigned long long key = ((unsigned long long)kb << 32)
                               | (unsigned int)bidx[k];
        atomicMin(&g_minkey[(size_t)b * NN + n], key);
    }
}

// Decode winning (score, group) per point, recover first-index within the
// 8-face group by exact bit-equality rescan, hinge loss, reduce.
// Last block finalizes d_out.
__global__ __launch_bounds__(128)
void reduce_kernel(const float* __restrict__ pred, float* __restrict__ out,
                   int nblocks) {
    __shared__ double s_loss[4];
    __shared__ double s_cnt[4];

    int t = blockIdx.x * blockDim.x + threadIdx.x;   // [0, BB*NN)
    int b = t / NN;

    unsigned long long key = g_minkey[t];
    unsigned int kb = (unsigned int)(key >> 32);
    unsigned int sb = (kb & 0x80000000u) ? (kb & 0x7FFFFFFFu) : ~kb;
    int gbase = (int)(unsigned int)(key & 0xFFFFFFFFu);

    const float* pp = pred + (size_t)t * 3;
    float px = __ldg(pp + 0), py = __ldg(pp + 1), pz = __ldg(pp + 2);
    float qx = -2.0f * px, qy = -2.0f * py, qz = -2.0f * pz;

    // Recover first matching index within the winning group of 8. FMNMX
    // propagates exact lane bits and scalar fma.rn == per-lane fma.rn.f32x2,
    // so bit-equality finds the true winner; min over ascending candidate
    // indices == first index (JAX tie-break).
    int widx = 0x7fffffff;
    const float4* cb = g_c4 + (size_t)b * FF;
#pragma unroll
    for (int jj = 0; jj < 8; jj++) {
        float4 cj = cb[gbase + jj];
        float sj = fmaf(qx, cj.x, fmaf(qy, cj.y, fmaf(qz, cj.z, cj.w)));
        int cand = (__float_as_uint(sj) == sb) ? (gbase + jj) : 0x7fffffff;
        widx = min(widx, cand);
    }
    if (widx == 0x7fffffff) widx = gbase;   // unreachable safety guard

    float4 c  = g_c4[(size_t)b * FF + widx];
    float4 nr = g_nrm[(size_t)b * FF + widx];
    float d = (px - c.x) * nr.x + (py - c.y) * nr.y + (pz - c.z) * nr.z;
    float interp = fmaxf(EPS_C - d, 0.0f);

    double l  = (double)(interp * interp * interp);
    double cc = (interp > 0.0f) ? 1.0 : 0.0;

    int lane = threadIdx.x & 31;
    int warp = threadIdx.x >> 5;
#pragma unroll
    for (int off = 16; off > 0; off >>= 1) {
        l  += __shfl_down_sync(0xffffffffu, l, off);
        cc += __shfl_down_sync(0xffffffffu, cc, off);
    }
    if (lane == 0) { s_loss[warp] = l; s_cnt[warp] = cc; }
    __syncthreads();
    if (warp == 0 && lane == 0) {
        double L = s_loss[0] + s_loss[1] + s_loss[2] + s_loss[3];
        double C = s_cnt[0] + s_cnt[1] + s_cnt[2] + s_cnt[3];
        atomicAdd(&g_acc[0], L);
        atomicAdd(&g_acc[1], C);
        __threadfence();
        int done = atomicAdd(&g_done, 1);
        if (done == nblocks - 1) {
            double totL = atomicAdd(&g_acc[0], 0.0);
            double totC = atomicAdd(&g_acc[1], 0.0);
            out[0] = (float)(totL / (double)BB * WEIGHT_C);
            out[1] = (float)(totC / (double)(BB * NN));
        }
    }
}

extern "C" void kernel_launch(void* const* d_in, const int* in_sizes, int n_in,
                              void* d_out, int out_size) {
    const float* pred  = (const float*)d_in[0];   // [B,N,3] f32
    const float* opos  = (const float*)d_in[1];   // [B,V,3] f32
    const int*   faces = (const int*)d_in[2];     // [B,F,3] i32
    float* out = (float*)d_out;

    faces_kernel<<<(BB * FF + 255) / 256, 256>>>(opos, faces);
    scan_kernel<<<dim3(NN / PTS_PER_BLOCK, SS, BB), SCAN_THREADS>>>(pred);
    int rblocks = (BB * NN) / 128;
    reduce_kernel<<<rblocks, 128>>>(pred, out, rblocks);
}

// round 17
// speedup vs baseline: 1.0453x; 1.0208x over previous
#include <cuda_runtime.h>
#include <math.h>

#define BB 4
#define VV 8192
#define FF 16384
#define NN 8192
#define SS 32                      // F-chunks per batch
#define CHUNK (FF / SS)            // 512 faces per block
#define NPAIR (CHUNK / 2)          // 256 face-pairs per tile
#define SEGF 64                    // faces per index segment
#define NSEG (CHUNK / SEGF)        // 8 segments per chunk
#define GPS (SEGF / 8)             // 8 groups (of 8 faces) per segment
#define SCAN_THREADS 128
#define PT 8                       // points per thread
#define PTS_PER_BLOCK (SCAN_THREADS * PT)   // 1024
#define EPS_C 1e-3f
#define WEIGHT_C 1000.0

// ---- scratch (no allocations allowed) ----
__device__ float4 g_c4[BB * FF];        // (cx, cy, cz, |c|^2)
__device__ float4 g_nrm[BB * FF];       // unit normal
__device__ unsigned long long g_minkey[BB * NN];  // (sortable score | seg base)
__device__ double g_acc[2];             // [0]=sum interp^3, [1]=count(interp>0)
__device__ int    g_done;

// ---- packed f32x2 helpers (sm_103a) ----
__device__ __forceinline__ unsigned long long pack2(float lo, float hi) {
    unsigned long long r;
    asm("mov.b64 %0, {%1, %2};" : "=l"(r) : "f"(lo), "f"(hi));
    return r;
}
__device__ __forceinline__ unsigned long long fma2(unsigned long long a,
                                                   unsigned long long b,
                                                   unsigned long long c) {
    unsigned long long d;
    asm("fma.rn.f32x2 %0, %1, %2, %3;" : "=l"(d) : "l"(a), "l"(b), "l"(c));
    return d;
}
__device__ __forceinline__ void unpack2(unsigned long long v, float& lo, float& hi) {
    asm("mov.b64 {%0, %1}, %2;" : "=f"(lo), "=f"(hi) : "l"(v));
}

// One thread per face: center, |center|^2, unit normal. Also inits g_minkey
// (BB*NN entries <= BB*FF threads) and accumulators.
__global__ void faces_kernel(const float* __restrict__ opos,
                             const int* __restrict__ faces) {
    int t = blockIdx.x * blockDim.x + threadIdx.x;
    if (t == 0) { g_acc[0] = 0.0; g_acc[1] = 0.0; g_done = 0; }
    if (t < BB * NN) g_minkey[t] = ~0ull;
    if (t >= BB * FF) return;
    int b = t / FF;
    const int* fp = faces + (size_t)t * 3;
    int i0 = fp[0], i1 = fp[1], i2 = fp[2];
    const float* pb = opos + (size_t)b * VV * 3;

    float x0 = __ldg(pb + i0 * 3 + 0), y0 = __ldg(pb + i0 * 3 + 1), z0 = __ldg(pb + i0 * 3 + 2);
    float x1 = __ldg(pb + i1 * 3 + 0), y1 = __ldg(pb + i1 * 3 + 1), z1 = __ldg(pb + i1 * 3 + 2);
    float x2 = __ldg(pb + i2 * 3 + 0), y2 = __ldg(pb + i2 * 3 + 1), z2 = __ldg(pb + i2 * 3 + 2);

    const float third = 1.0f / 3.0f;
    float cx = (x0 + x1 + x2) * third;
    float cy = (y0 + y1 + y2) * third;
    float cz = (z0 + z1 + z2) * third;

    float e1x = x1 - x0, e1y = y1 - y0, e1z = z1 - z0;
    float e2x = x2 - x0, e2y = y2 - y0, e2z = z2 - z0;
    float nx = e1y * e2z - e1z * e2y;
    float ny = e1z * e2x - e1x * e2z;
    float nz = e1x * e2y - e1y * e2x;
    float len = sqrtf(nx * nx + ny * ny + nz * nz);
    float inv = 1.0f / fmaxf(len, 1e-12f);

    g_c4[t]  = make_float4(cx, cy, cz, cx * cx + cy * cy + cz * cz);
    g_nrm[t] = make_float4(nx * inv, ny * inv, nz * inv, 0.0f);
}

// Each block: 1024 points x 512-face chunk (grid 8x32x4 = 1024 blocks).
// SMEM tile packs FACE PAIRS as f32x2 words. Inner loop per 8-face group:
// operands loaded ONCE into registers, then per point 12 FFMA2 + 4 pair-min
// + 4 FOLDS into a running prefix-min — no per-group select. Index tracking
// happens per 64-face SEGMENT: strict-< improvement of the prefix-min marks
// the EARLIEST segment containing the global min. Chunks merge globally via
// atomicMin on a packed 64-bit key (monotone score bits << 32 | seg base).
// First-index recovery within the winning 64-face segment happens in
// reduce_kernel via ascending exact bit-equality rescan — together this
// reproduces JAX first-index argmin semantics exactly.
__global__ __launch_bounds__(SCAN_THREADS)
void scan_kernel(const float* __restrict__ pred) {
    __shared__ ulonglong2 tA[NPAIR];   // ((x,x'),(y,y'))
    __shared__ ulonglong2 tB[NPAIR];   // ((z,z'),(w,w'))

    int b = blockIdx.z;
    int s = blockIdx.y;
    int pbase = blockIdx.x * PTS_PER_BLOCK;
    int tid = threadIdx.x;
    int fbase = s * CHUNK;

    const float4* cbase = g_c4 + (size_t)b * FF + fbase;
    for (int m = tid; m < NPAIR; m += SCAN_THREADS) {
        float4 c0 = cbase[2 * m];
        float4 c1 = cbase[2 * m + 1];
        tA[m].x = pack2(c0.x, c1.x);
        tA[m].y = pack2(c0.y, c1.y);
        tB[m].x = pack2(c0.z, c1.z);
        tB[m].y = pack2(c0.w, c1.w);
    }

    // q = -2p broadcast-packed per point.
    unsigned long long qx2[PT], qy2[PT], qz2[PT];
    float best[PT], run[PT];
    int sbase[PT];
#pragma unroll
    for (int k = 0; k < PT; k++) {
        int n = pbase + k * SCAN_THREADS + tid;
        const float* pp = pred + ((size_t)b * NN + n) * 3;
        float qx = -2.0f * __ldg(pp + 0);
        float qy = -2.0f * __ldg(pp + 1);
        float qz = -2.0f * __ldg(pp + 2);
        qx2[k] = pack2(qx, qx);
        qy2[k] = pack2(qy, qy);
        qz2[k] = pack2(qz, qz);
        best[k] = 3.4e38f;
        run[k]  = 3.4e38f;
        sbase[k] = 0;
    }
    __syncthreads();

    for (int seg = 0; seg < NSEG; seg++) {
#pragma unroll 2
        for (int gg = 0; gg < GPS; gg++) {
            int m0 = (seg * GPS + gg) * 4;
            // group operands loaded ONCE, reused by all PT points
            ulonglong2 a0 = tA[m0 + 0], v0 = tB[m0 + 0];
            ulonglong2 a1 = tA[m0 + 1], v1 = tB[m0 + 1];
            ulonglong2 a2 = tA[m0 + 2], v2 = tB[m0 + 2];
            ulonglong2 a3 = tA[m0 + 3], v3 = tB[m0 + 3];
#pragma unroll
            for (int k = 0; k < PT; k++) {
                // per-lane: ((qz*z + w) + qy*y) + qx*x — same fma order as R1
                unsigned long long s0 = fma2(qz2[k], v0.x, v0.y);
                unsigned long long s1 = fma2(qz2[k], v1.x, v1.y);
                unsigned long long s2 = fma2(qz2[k], v2.x, v2.y);
                unsigned long long s3 = fma2(qz2[k], v3.x, v3.y);
                s0 = fma2(qy2[k], a0.y, s0);
                s1 = fma2(qy2[k], a1.y, s1);
                s2 = fma2(qy2[k], a2.y, s2);
                s3 = fma2(qy2[k], a3.y, s3);
                s0 = fma2(qx2[k], a0.x, s0);
                s1 = fma2(qx2[k], a1.x, s1);
                s2 = fma2(qx2[k], a2.x, s2);
                s3 = fma2(qx2[k], a3.x, s3);
                float l0, h0, l1, h1, l2, h2, l3, h3;
                unpack2(s0, l0, h0);
                unpack2(s1, l1, h1);
                unpack2(s2, l2, h2);
                unpack2(s3, l3, h3);
                // pair-mins folded straight into the running prefix-min
                best[k] = fminf(best[k], fminf(l0, h0));
                best[k] = fminf(best[k], fminf(l1, h1));
                best[k] = fminf(best[k], fminf(l2, h2));
                best[k] = fminf(best[k], fminf(l3, h3));
            }
        }
        // segment bookkeeping: prefix-min is monotone; strict < records the
        // EARLIEST segment achieving the final minimum.
        int jv = fbase + seg * SEGF;
#pragma unroll
        for (int k = 0; k < PT; k++) {
            if (best[k] < run[k]) { run[k] = best[k]; sbase[k] = jv; }
        }
    }

    // Global merge: packed sortable key, REDG.MIN.U64 (no return).
#pragma unroll
    for (int k = 0; k < PT; k++) {
        int n = pbase + k * SCAN_THREADS + tid;
        unsigned int sb = __float_as_uint(run[k]);
        unsigned int kb = (sb & 0x80000000u) ? ~sb : (sb | 0x80000000u);
        unsigned long long key = ((unsigned long long)kb << 32)
                               | (unsigned int)sbase[k];
        atomicMin(&g_minkey[(size_t)b * NN + n], key);
    }
}

// Decode winning (score, segment) per point, recover first-index within the
// 64-face segment by ascending exact bit-equality rescan, hinge loss, reduce.
// Last block finalizes d_out.
__global__ __launch_bounds__(128)
void reduce_kernel(const float* __restrict__ pred, float* __restrict__ out,
                   int nblocks) {
    __shared__ double s_loss[4];
    __shared__ double s_cnt[4];

    int t = blockIdx.x * blockDim.x + threadIdx.x;   // [0, BB*NN)
    int b = t / NN;

    unsigned long long key = g_minkey[t];
    unsigned int kb = (unsigned int)(key >> 32);
    unsigned int sb = (kb & 0x80000000u) ? (kb & 0x7FFFFFFFu) : ~kb;
    int gbase = (int)(unsigned int)(key & 0xFFFFFFFFu);

    const float* pp = pred + (size_t)t * 3;
    float px = __ldg(pp + 0), py = __ldg(pp + 1), pz = __ldg(pp + 2);
    float qx = -2.0f * px, qy = -2.0f * py, qz = -2.0f * pz;

    // Recover first matching index within the winning 64-face segment.
    // FMNMX folds propagate exact lane bits and scalar fma.rn == per-lane
    // fma.rn.f32x2, so bit-equality finds the true winner; min over
    // ascending candidate indices == first index (JAX tie-break).
    int widx = 0x7fffffff;
    const float4* cb = g_c4 + (size_t)b * FF;
#pragma unroll 8
    for (int jj = 0; jj < SEGF; jj++) {
        float4 cj = cb[gbase + jj];
        float sj = fmaf(qx, cj.x, fmaf(qy, cj.y, fmaf(qz, cj.z, cj.w)));
        int cand = (__float_as_uint(sj) == sb) ? (gbase + jj) : 0x7fffffff;
        widx = min(widx, cand);
    }
    if (widx == 0x7fffffff) widx = gbase;   // unreachable safety guard

    float4 c  = g_c4[(size_t)b * FF + widx];
    float4 nr = g_nrm[(size_t)b * FF + widx];
    float d = (px - c.x) * nr.x + (py - c.y) * nr.y + (pz - c.z) * nr.z;
    float interp = fmaxf(EPS_C - d, 0.0f);

    double l  = (double)(interp * interp * interp);
    double cc = (interp > 0.0f) ? 1.0 : 0.0;

    int lane = threadIdx.x & 31;
    int warp = threadIdx.x >> 5;
#pragma unroll
    for (int off = 16; off > 0; off >>= 1) {
        l  += __shfl_down_sync(0xffffffffu, l, off);
        cc += __shfl_down_sync(0xffffffffu, cc, off);
    }
    if (lane == 0) { s_loss[warp] = l; s_cnt[warp] = cc; }
    __syncthreads();
    if (warp == 0 && lane == 0) {
        double L = s_loss[0] + s_loss[1] + s_loss[2] + s_loss[3];
        double C = s_cnt[0] + s_cnt[1] + s_cnt[2] + s_cnt[3];
        atomicAdd(&g_acc[0], L);
        atomicAdd(&g_acc[1], C);
        __threadfence();
        int done = atomicAdd(&g_done, 1);
        if (done == nblocks - 1) {
            double totL = atomicAdd(&g_acc[0], 0.0);
            double totC = atomicAdd(&g_acc[1], 0.0);
            out[0] = (float)(totL / (double)BB * WEIGHT_C);
            out[1] = (float)(totC / (double)(BB * NN));
        }
    }
}

extern "C" void kernel_launch(void* const* d_in, const int* in_sizes, int n_in,
                              void* d_out, int out_size) {
    const float* pred  = (const float*)d_in[0];   // [B,N,3] f32
    const float* opos  = (const float*)d_in[1];   // [B,V,3] f32
    const int*   faces = (const int*)d_in[2];     // [B,F,3] i32
    float* out = (float*)d_out;

    faces_kernel<<<(BB * FF + 255) / 256, 256>>>(opos, faces);
    scan_kernel<<<dim3(NN / PTS_PER_BLOCK, SS, BB), SCAN_THREADS>>>(pred);
    int rblocks = (BB * NN) / 128;
    reduce_kernel<<<rblocks, 128>>>(pred, out, rblocks);
}